// round 1
// baseline (speedup 1.0000x reference)
#include <cuda_runtime.h>
#include <cuda_bf16.h>

// Problem constants (fixed by the dataset: feats [8,64,32,32], N=1024 boxes)
#define B_    8
#define C_    64
#define H_    32
#define W_    32
#define HOUT  8
#define WOUT  8
#define MAXG  4

// Channels-last scratch: [B][H][W][C]  (8*32*32*64 floats = 8 MB)
__device__ float g_cl[B_ * H_ * W_ * C_];

// ---------------------------------------------------------------------------
// Kernel 1: transpose feats [B,C,H,W] -> g_cl [B,H,W,C]
// grid: (B*H, C/32), block: (32, 8). Coalesced load over x, coalesced store over c.
// ---------------------------------------------------------------------------
__global__ void transpose_kernel(const float* __restrict__ feats) {
    __shared__ float tile[32][33];
    const int b  = blockIdx.x >> 5;
    const int y  = blockIdx.x & 31;
    const int c0 = blockIdx.y << 5;
    const int tx = threadIdx.x;
    const int ty = threadIdx.y;

    const float* src = feats + ((size_t)(b * C_ + c0) * H_ + y) * W_;
    #pragma unroll
    for (int cc = ty; cc < 32; cc += 8)
        tile[cc][tx] = src[(size_t)cc * (H_ * W_) + tx];
    __syncthreads();

    float* dst = g_cl + ((size_t)(b * H_ + y) * W_) * C_ + c0;
    #pragma unroll
    for (int xx = ty; xx < 32; xx += 8)
        dst[(size_t)xx * C_ + tx] = tile[tx][xx];
}

// ---------------------------------------------------------------------------
// Kernel 2: one block per box. 256 threads = 8 warps.
//   warp w: channel group (w & 1) -> channels [32*(w&1) .. +32), lane = channel
//           bins: (w>>1) + 4*t for t in 0..15
// Sampling metadata (per box, channel-independent) computed by threads 0..63.
// Results staged in smem (pitch 65), flipped + written coalesced.
// ---------------------------------------------------------------------------
__global__ __launch_bounds__(256, 4)
void roi_kernel(const int* __restrict__ batch_idxs,
                const int* __restrict__ starts,
                const int* __restrict__ goals,
                float* __restrict__ out) {
    const int n   = blockIdx.x;
    const int tid = threadIdx.x;

    __shared__ float s_rois[C_ * 65];          // [c][bin] pitch 65 (conflict-free)
    __shared__ int   s_lo[64], s_hi[64];       // [axis*32 + ph*4 + i], axis 0=y,1=x
    __shared__ float s_w0[64], s_w1[64];
    __shared__ int   s_gh, s_gw, s_case, s_b;
    __shared__ float s_invcnt;

    if (tid < 64) {
        // Per-box geometry (broadcast loads; every thread recomputes)
        const float sy = (float)starts[2 * n + 0];
        const float sx = (float)starts[2 * n + 1];
        const float gy = (float)goals[2 * n + 0];
        const float gx = (float)goals[2 * n + 1];
        const float y_min = fminf(sy, gy), y_max = fmaxf(sy, gy);
        const float x_min = fminf(sx, gx), x_max = fmaxf(sx, gx);

        const float start_h = y_min - 0.5f;
        const float start_w = x_min - 0.5f;
        const float bin_h = (y_max - y_min) / (float)HOUT;
        const float bin_w = (x_max - x_min) / (float)WOUT;
        const int gh = (int)ceilf(bin_h);
        const int gw = (int)ceilf(bin_w);

        const int axis = tid >> 5;           // 0 = y, 1 = x
        const int idx  = tid & 31;
        const int ph   = idx >> 2;
        const int i    = idx & 3;

        const float start  = axis ? start_w : start_h;
        const float bin_sz = axis ? bin_w  : bin_h;
        const int   grid   = axis ? gw     : gh;
        const float size   = 32.0f;          // H == W == 32

        const float g_safe = fmaxf((float)grid, 1.0f);
        const float step   = bin_sz / g_safe;
        const float pos    = start + (float)ph * bin_sz + ((float)i + 0.5f) * step;
        const bool  valid  = (pos >= -1.0f) && (pos <= size) && (i < grid);
        const float p      = fminf(fmaxf(pos, 0.0f), size - 1.0f);
        const float lowf   = floorf(p);
        const int   low    = (int)lowf;
        const int   high   = min(low + 1, (int)size - 1);
        const float l      = p - lowf;
        const float vf     = valid ? 1.0f : 0.0f;

        s_lo[tid] = low;
        s_hi[tid] = high;
        s_w0[tid] = (1.0f - l) * vf;
        s_w1[tid] = l * vf;

        if (tid == 0) {
            s_gh = gh; s_gw = gw;
            const int cnt = max(gh * gw, 1);
            s_invcnt = 1.0f / (float)cnt;
            const int y_rev = (sy > gy) ? 1 : 0;
            const int x_rev = (sx > gx) ? 1 : 0;
            s_case = y_rev * 2 + x_rev;
            s_b = batch_idxs[n];
        }
    }
    __syncthreads();

    const int   gh   = s_gh;
    const int   gw   = s_gw;
    const float invc = s_invcnt;
    const int   warp = tid >> 5;
    const int   lane = tid & 31;
    const int   c    = ((warp & 1) << 5) + lane;   // channel handled by this lane

    const float* __restrict__ fb = g_cl + (size_t)s_b * (H_ * W_ * C_) + c;

    #pragma unroll 1
    for (int t = 0; t < 16; t++) {
        const int bin = (warp >> 1) + (t << 2);    // 0..63
        const int oy  = bin >> 3;
        const int ox  = bin & 7;
        float acc = 0.0f;

        for (int iy = 0; iy < gh; iy++) {
            const int   yl  = s_lo[oy * 4 + iy];
            const int   yh  = s_hi[oy * 4 + iy];
            const float wy0 = s_w0[oy * 4 + iy];
            const float wy1 = s_w1[oy * 4 + iy];
            const float* r0 = fb + (size_t)yl * (W_ * C_);
            const float* r1 = fb + (size_t)yh * (W_ * C_);
            #pragma unroll 4
            for (int ix = 0; ix < gw; ix++) {
                const int   xidx = 32 + ox * 4 + ix;
                const int   xl   = s_lo[xidx];
                const int   xh   = s_hi[xidx];
                const float wx0  = s_w0[xidx];
                const float wx1  = s_w1[xidx];
                const float f00 = __ldg(r0 + (size_t)xl * C_);
                const float f01 = __ldg(r0 + (size_t)xh * C_);
                const float f10 = __ldg(r1 + (size_t)xl * C_);
                const float f11 = __ldg(r1 + (size_t)xh * C_);
                acc += wy0 * (wx0 * f00 + wx1 * f01)
                     + wy1 * (wx0 * f10 + wx1 * f11);
            }
        }
        s_rois[c * 65 + bin] = acc * invc;
    }
    __syncthreads();

    // Flip gather + coalesced write of the contiguous [C,8,8] slab for box n.
    // Flip table (replicating the reference's quirky construction):
    //   case 0            : src = y*8 + x           (identity)
    //   case 1 and case 2 : src = y*8 + (7 - y)     (per-row broadcast)
    //   case 3            : src = (7-y)*8 + x       (row reversal only)
    const int cse = s_case;
    float* __restrict__ ob = out + (size_t)n * (C_ * HOUT * WOUT);
    #pragma unroll
    for (int k = tid; k < C_ * HOUT * WOUT; k += 256) {
        const int c2  = k >> 6;
        const int pos = k & 63;
        const int y   = pos >> 3;
        const int x   = pos & 7;
        int src;
        if      (cse == 0) src = pos;
        else if (cse == 3) src = ((7 - y) << 3) + x;
        else               src = (y << 3) + (7 - y);
        ob[k] = s_rois[c2 * 65 + src];
    }
}

extern "C" void kernel_launch(void* const* d_in, const int* in_sizes, int n_in,
                              void* d_out, int out_size) {
    const float* feats      = (const float*)d_in[0];
    const int*   batch_idxs = (const int*)d_in[1];
    const int*   starts     = (const int*)d_in[2];
    const int*   goals      = (const int*)d_in[3];
    float*       out        = (float*)d_out;

    const int N = in_sizes[1];   // number of boxes (1024)

    dim3 tgrid(B_ * H_, C_ / 32);
    dim3 tblock(32, 8);
    transpose_kernel<<<tgrid, tblock>>>(feats);

    roi_kernel<<<N, 256>>>(batch_idxs, starts, goals, out);
}

// round 2
// speedup vs baseline: 1.2078x; 1.2078x over previous
#include <cuda_runtime.h>
#include <cuda_bf16.h>

// Problem constants (fixed by dataset: feats [8,64,32,32], N boxes)
#define B_    8
#define C_    64
#define H_    32
#define W_    32
#define HOUT  8
#define WOUT  8
#define MAXG  4

#define CH    32                 // channels per half
#define TPITCH (CH * W_ + 8)     // tmp pitch per oy: 1032 floats (oy bank shift = 8)

// ---------------------------------------------------------------------------
// One block per box. 256 threads. Separable formulation:
//   out[oy][ox][c] = sum_y sum_x Wy[y][oy] * Wx[x][ox] * f[c][y][x]
// Wy scaled by 1/count. Two channel halves to keep smem ~35KB (4 blocks/SM).
// ---------------------------------------------------------------------------
__global__ __launch_bounds__(256, 4)
void roi_kernel(const float* __restrict__ feats,
                const int* __restrict__ batch_idxs,
                const int* __restrict__ starts,
                const int* __restrict__ goals,
                float* __restrict__ out) {
    const int n   = blockIdx.x;
    const int tid = threadIdx.x;

    __shared__ float s_tmp[HOUT * TPITCH];  // [oy][c_local][x], padded
    __shared__ float s_Wy[H_ * HOUT];       // [y][oy]
    __shared__ float s_Wx[W_ * WOUT];       // [x][ox]
    __shared__ int   s_y0, s_ny, s_x0, s_nx, s_case, s_b;

    // --- zero weight matrices ---
    if (tid < 256) { s_Wy[tid] = 0.0f; s_Wx[tid] = 0.0f; }
    __syncthreads();

    // --- per-box geometry + sample scatter (threads 0..63) ---
    if (tid < 64) {
        const float sy = (float)starts[2 * n + 0];
        const float sx = (float)starts[2 * n + 1];
        const float gy = (float)goals[2 * n + 0];
        const float gx = (float)goals[2 * n + 1];
        const float y_min = fminf(sy, gy), y_max = fmaxf(sy, gy);
        const float x_min = fminf(sx, gx), x_max = fmaxf(sx, gx);

        const float start_h = y_min - 0.5f;
        const float start_w = x_min - 0.5f;
        const float bin_h = (y_max - y_min) / (float)HOUT;
        const float bin_w = (x_max - x_min) / (float)WOUT;
        const int gh = (int)ceilf(bin_h);
        const int gw = (int)ceilf(bin_w);
        const float invc = 1.0f / (float)max(gh * gw, 1);

        const int axis = tid >> 5;           // 0 = y, 1 = x
        const int idx  = tid & 31;
        const int ph   = idx >> 2;           // output bin along this axis
        const int i    = idx & 3;            // adaptive sample index

        const float start  = axis ? start_w : start_h;
        const float bin_sz = axis ? bin_w  : bin_h;
        const int   grid   = axis ? gw     : gh;
        const float size   = 32.0f;

        const float g_safe = fmaxf((float)grid, 1.0f);
        const float pos    = start + (float)ph * bin_sz
                           + ((float)i + 0.5f) * (bin_sz / g_safe);
        const bool  valid  = (pos >= -1.0f) && (pos <= size) && (i < grid);
        const float p      = fminf(fmaxf(pos, 0.0f), size - 1.0f);
        const float lowf   = floorf(p);
        const int   low    = (int)lowf;
        const int   high   = min(low + 1, (int)size - 1);
        const float l      = p - lowf;
        const float vf     = valid ? 1.0f : 0.0f;
        const float scale  = axis ? 1.0f : invc;   // fold 1/count into Wy

        float* Wm = axis ? s_Wx : s_Wy;
        atomicAdd(&Wm[low  * 8 + ph], (1.0f - l) * vf * scale);
        atomicAdd(&Wm[high * 8 + ph], l * vf * scale);

        if (tid == 0) {
            const int y_rev = (sy > gy) ? 1 : 0;
            const int x_rev = (sx > gx) ? 1 : 0;
            s_case = y_rev * 2 + x_rev;
            s_b = batch_idxs[n];
        }
    }
    __syncthreads();

    // --- active row/col range detection (warp 0: y, warp 1: x) ---
    if (tid < 32) {
        float s = 0.0f;
        #pragma unroll
        for (int oy = 0; oy < 8; oy++) s += fabsf(s_Wy[tid * 8 + oy]);
        unsigned m = __ballot_sync(0xffffffffu, s != 0.0f);
        if (tid == 0) {
            s_y0 = m ? (__ffs(m) - 1) : 0;
            s_ny = m ? (32 - __clz(m)) - (__ffs(m) - 1) : 0;
        }
    } else if (tid < 64) {
        const int lane = tid - 32;
        float s = 0.0f;
        #pragma unroll
        for (int ox = 0; ox < 8; ox++) s += fabsf(s_Wx[lane * 8 + ox]);
        unsigned m = __ballot_sync(0xffffffffu, s != 0.0f);
        if (lane == 0) {
            s_x0 = m ? (__ffs(m) - 1) : 0;
            s_nx = m ? (32 - __clz(m)) - (__ffs(m) - 1) : 0;
        }
    }
    __syncthreads();

    const int y0 = s_y0, ny = s_ny, x0 = s_x0, nx = s_nx;
    const int b  = s_b,  cse = s_case;

    // pass-A thread mapping: lane over x (coalesced rows), columns over c
    const int xlane = tid & 31;
    const int cbase = tid >> 5;      // 0..7
    // pass-B thread mapping: contiguous output positions
    const int pos = tid & 63;
    const int c0  = tid >> 6;        // 0..3
    const int py  = pos >> 3;
    const int px  = pos & 7;
    int oy_s, ox_s;                  // source bin after (inverse) flip
    if      (cse == 0) { oy_s = py;     ox_s = px;     }
    else if (cse == 3) { oy_s = 7 - py; ox_s = px;     }
    else               { oy_s = py;     ox_s = 7 - py; }

    const float* __restrict__ fB = feats + (size_t)b * (C_ * H_ * W_);
    float* __restrict__ ob = out + (size_t)n * (C_ * HOUT * WOUT);

    #pragma unroll
    for (int h = 0; h < 2; h++) {
        // ---- Pass A: tmp[oy][cl][x] = sum_y Wy[y][oy] * f[c][y][x] ----
        #pragma unroll
        for (int r = 0; r < 4; r++) {
            const int cl = cbase + 8 * r;            // local channel 0..31
            const int c  = CH * h + cl;
            const float* fp = fB + (size_t)c * (H_ * W_) + y0 * W_ + xlane;
            float a0 = 0, a1 = 0, a2 = 0, a3 = 0, a4 = 0, a5 = 0, a6 = 0, a7 = 0;
            #pragma unroll 4
            for (int yy = 0; yy < ny; yy++) {
                const float v = __ldg(fp + yy * W_);
                const float4 wA = *reinterpret_cast<const float4*>(&s_Wy[(y0 + yy) * 8]);
                const float4 wB = *reinterpret_cast<const float4*>(&s_Wy[(y0 + yy) * 8 + 4]);
                a0 += v * wA.x; a1 += v * wA.y; a2 += v * wA.z; a3 += v * wA.w;
                a4 += v * wB.x; a5 += v * wB.y; a6 += v * wB.z; a7 += v * wB.w;
            }
            float* tp = s_tmp + cl * W_ + xlane;
            tp[0 * TPITCH] = a0; tp[1 * TPITCH] = a1;
            tp[2 * TPITCH] = a2; tp[3 * TPITCH] = a3;
            tp[4 * TPITCH] = a4; tp[5 * TPITCH] = a5;
            tp[6 * TPITCH] = a6; tp[7 * TPITCH] = a7;
        }
        __syncthreads();

        // ---- Pass B: out[c][pos] = sum_x Wx[x][ox_s] * tmp[oy_s][cl][x] ----
        {
            float acc[8];
            #pragma unroll
            for (int r = 0; r < 8; r++) acc[r] = 0.0f;
            const float* tp = s_tmp + oy_s * TPITCH + c0 * W_;
            for (int k = 0; k < nx; k++) {
                const int x = x0 + k;
                const float wx = s_Wx[x * 8 + ox_s];
                #pragma unroll
                for (int r = 0; r < 8; r++)
                    acc[r] += wx * tp[(4 * r) * W_ + x];
            }
            float* op = ob + (size_t)(CH * h + c0) * 64 + pos;
            #pragma unroll
            for (int r = 0; r < 8; r++)
                op[(size_t)(4 * r) * 64] = acc[r];
        }
        if (h == 0) __syncthreads();   // tmp reused by half 1
    }
}

extern "C" void kernel_launch(void* const* d_in, const int* in_sizes, int n_in,
                              void* d_out, int out_size) {
    const float* feats      = (const float*)d_in[0];
    const int*   batch_idxs = (const int*)d_in[1];
    const int*   starts     = (const int*)d_in[2];
    const int*   goals      = (const int*)d_in[3];
    float*       out        = (float*)d_out;

    const int N = in_sizes[1];   // number of boxes (1024)

    roi_kernel<<<N, 256>>>(feats, batch_idxs, starts, goals, out);
}

// round 3
// speedup vs baseline: 1.6870x; 1.3967x over previous
#include <cuda_runtime.h>
#include <cuda_bf16.h>

// Problem constants (fixed by dataset: feats [8,64,32,32], N boxes)
#define B_    8
#define C_    64
#define H_    32
#define W_    32
#define HOUT  8
#define WOUT  8

#define TP    (32 * 32 + 8)   // s_tmp pitch per oy (floats): bank shift 8, 16B-aligned
#define WXP   40              // s_WxT row pitch (floats): 160B, 16B-aligned, bank shift 8

#define PACK2(d, lo, hi) asm("mov.b64 %0, {%1, %2};" : "=l"(d) : "f"(lo), "f"(hi))
#define UNPK2(lo, hi, s) asm("mov.b64 {%0, %1}, %2;" : "=f"(lo), "=f"(hi) : "l"(s))
#define FMA2(d, a, b, c) asm("fma.rn.f32x2 %0, %1, %2, %3;" : "=l"(d) : "l"(a), "l"(b), "l"(c))

// ---------------------------------------------------------------------------
// grid (N, 2): block handles one box (blockIdx.x) x one 32-channel half
// (blockIdx.y). 256 threads = 8 warps.
// Separable: out[oy][ox][c] = sum_y sum_x Wy[y][oy] * Wx[x][ox] * f[c][y][x]
// (1/count folded into Wy).
// ---------------------------------------------------------------------------
__global__ __launch_bounds__(256, 4)
void roi_kernel(const float* __restrict__ feats,
                const int* __restrict__ batch_idxs,
                const int* __restrict__ starts,
                const int* __restrict__ goals,
                float* __restrict__ out) {
    const int n   = blockIdx.x;
    const int h   = blockIdx.y;          // channel half
    const int tid = threadIdx.x;

    __shared__ float s_tmp[HOUT * TP];   // [oy][cl*32 + x]
    __shared__ float s_Wy[H_ * 8];       // [y][oy]
    __shared__ float s_WxT[8 * WXP];     // [ox][x]  (transposed for float4 reads)
    __shared__ int   s_y0, s_ny, s_xc0, s_ncx, s_case, s_b;

    // --- zero weight matrices ---
    s_Wy[tid] = 0.0f;                      // 256 == 32*8 exactly
    for (int k = tid; k < 8 * WXP; k += 256) s_WxT[k] = 0.0f;
    __syncthreads();

    // --- per-box geometry + sample scatter (threads 0..63) ---
    if (tid < 64) {
        const float sy = (float)starts[2 * n + 0];
        const float sx = (float)starts[2 * n + 1];
        const float gy = (float)goals[2 * n + 0];
        const float gx = (float)goals[2 * n + 1];
        const float y_min = fminf(sy, gy), y_max = fmaxf(sy, gy);
        const float x_min = fminf(sx, gx), x_max = fmaxf(sx, gx);

        const float start_h = y_min - 0.5f;
        const float start_w = x_min - 0.5f;
        const float bin_h = (y_max - y_min) / (float)HOUT;
        const float bin_w = (x_max - x_min) / (float)WOUT;
        const int gh = (int)ceilf(bin_h);
        const int gw = (int)ceilf(bin_w);
        const float invc = 1.0f / (float)max(gh * gw, 1);

        const int axis = tid >> 5;           // 0 = y, 1 = x
        const int idx  = tid & 31;
        const int ph   = idx >> 2;           // output bin along this axis
        const int i    = idx & 3;            // adaptive sample index

        const float start  = axis ? start_w : start_h;
        const float bin_sz = axis ? bin_w  : bin_h;
        const int   grid   = axis ? gw     : gh;
        const float size   = 32.0f;

        const float g_safe = fmaxf((float)grid, 1.0f);
        const float pos    = start + (float)ph * bin_sz
                           + ((float)i + 0.5f) * (bin_sz / g_safe);
        const bool  valid  = (pos >= -1.0f) && (pos <= size) && (i < grid);
        const float p      = fminf(fmaxf(pos, 0.0f), size - 1.0f);
        const float lowf   = floorf(p);
        const int   low    = (int)lowf;
        const int   high   = min(low + 1, (int)size - 1);
        const float l      = p - lowf;
        const float vf     = valid ? 1.0f : 0.0f;

        if (axis == 0) {
            atomicAdd(&s_Wy[low  * 8 + ph], (1.0f - l) * vf * invc);
            atomicAdd(&s_Wy[high * 8 + ph], l * vf * invc);
        } else {
            atomicAdd(&s_WxT[ph * WXP + low ], (1.0f - l) * vf);
            atomicAdd(&s_WxT[ph * WXP + high], l * vf);
        }

        if (tid == 0) {
            s_case = ((sy > gy) ? 2 : 0) + ((sx > gx) ? 1 : 0);
            s_b = batch_idxs[n];
        }
    }
    __syncthreads();

    // --- active range detection (warp 0: y rows, warp 1: x cols) ---
    if (tid < 32) {
        float s = 0.0f;
        #pragma unroll
        for (int oy = 0; oy < 8; oy++) s += s_Wy[tid * 8 + oy];   // weights >= 0
        unsigned m = __ballot_sync(0xffffffffu, s != 0.0f);
        if (tid == 0) {
            s_y0 = m ? (__ffs(m) - 1) : 0;
            s_ny = m ? (32 - __clz(m)) - (__ffs(m) - 1) : 0;
        }
    } else if (tid < 64) {
        const int lane = tid - 32;
        float s = 0.0f;
        #pragma unroll
        for (int ox = 0; ox < 8; ox++) s += s_WxT[ox * WXP + lane];
        unsigned m = __ballot_sync(0xffffffffu, s != 0.0f);
        if (lane == 0) {
            if (m) {
                const int x0 = __ffs(m) - 1;
                const int x1 = 32 - __clz(m);            // exclusive
                const int xc0 = x0 & ~3;
                s_xc0 = xc0;
                s_ncx = (x1 - xc0 + 3) >> 2;
            } else { s_xc0 = 0; s_ncx = 0; }
        }
    }
    __syncthreads();

    const int y0 = s_y0, ny = s_ny, xc0 = s_xc0, ncx = s_ncx;
    const int b  = s_b,  cse = s_case;

    // ---- Pass A: tmp[oy][cl][x] = sum_y Wy[y][oy] * f[c][y][x] ----
    // warp handles 4 channels: cc = lane>>3 (channel-in-warp), xg = lane&7 (x/4)
    {
        const int warp = tid >> 5;
        const int lane = tid & 31;
        const int cc   = lane >> 3;
        const int xg   = lane & 7;
        const int cl   = warp * 4 + cc;                // local channel 0..31
        const int c    = h * 32 + cl;
        const float* __restrict__ fp =
            feats + (size_t)(b * C_ + c) * (H_ * W_) + 4 * xg;

        unsigned long long acc[16];                    // [oy][pair], pair0={x0,x1}
        #pragma unroll
        for (int k = 0; k < 16; k++) acc[k] = 0ull;

        for (int yy = 0; yy < ny; yy++) {
            const int y = y0 + yy;
            const float4 v = __ldg((const float4*)(fp + y * W_));
            unsigned long long v01, v23;
            PACK2(v01, v.x, v.y);
            PACK2(v23, v.z, v.w);
            const float4 wA = *reinterpret_cast<const float4*>(&s_Wy[y * 8]);
            const float4 wB = *reinterpret_cast<const float4*>(&s_Wy[y * 8 + 4]);
            unsigned long long w;
            PACK2(w, wA.x, wA.x); FMA2(acc[0],  v01, w, acc[0]);  FMA2(acc[1],  v23, w, acc[1]);
            PACK2(w, wA.y, wA.y); FMA2(acc[2],  v01, w, acc[2]);  FMA2(acc[3],  v23, w, acc[3]);
            PACK2(w, wA.z, wA.z); FMA2(acc[4],  v01, w, acc[4]);  FMA2(acc[5],  v23, w, acc[5]);
            PACK2(w, wA.w, wA.w); FMA2(acc[6],  v01, w, acc[6]);  FMA2(acc[7],  v23, w, acc[7]);
            PACK2(w, wB.x, wB.x); FMA2(acc[8],  v01, w, acc[8]);  FMA2(acc[9],  v23, w, acc[9]);
            PACK2(w, wB.y, wB.y); FMA2(acc[10], v01, w, acc[10]); FMA2(acc[11], v23, w, acc[11]);
            PACK2(w, wB.z, wB.z); FMA2(acc[12], v01, w, acc[12]); FMA2(acc[13], v23, w, acc[13]);
            PACK2(w, wB.w, wB.w); FMA2(acc[14], v01, w, acc[14]); FMA2(acc[15], v23, w, acc[15]);
        }

        float* tp = s_tmp + cl * 32 + 4 * xg;
        #pragma unroll
        for (int oy = 0; oy < 8; oy++) {
            float4 r;
            UNPK2(r.x, r.y, acc[2 * oy]);
            UNPK2(r.z, r.w, acc[2 * oy + 1]);
            *reinterpret_cast<float4*>(tp + oy * TP) = r;
        }
    }
    __syncthreads();

    // ---- Pass B: out[c][py][px] = sum_x Wx[x][ox_s] * tmp[oy_s][cl][x] ----
    {
        const int pos  = tid & 63;
        const int cgrp = tid >> 6;           // 0..3, channels cgrp*8 .. +7
        const int py   = pos >> 3;
        const int px   = pos & 7;
        int oy_s, ox_s;                      // source bin after flip
        if      (cse == 0) { oy_s = py;     ox_s = px;     }
        else if (cse == 3) { oy_s = 7 - py; ox_s = px;     }
        else               { oy_s = py;     ox_s = 7 - py; }

        float acc[8];
        #pragma unroll
        for (int r = 0; r < 8; r++) acc[r] = 0.0f;

        const float* wrow = s_WxT + ox_s * WXP;
        const float* trow = s_tmp + oy_s * TP + cgrp * 8 * 32;

        for (int k = 0; k < ncx; k++) {
            const int x4 = xc0 + 4 * k;
            const float4 wv = *reinterpret_cast<const float4*>(wrow + x4);
            #pragma unroll
            for (int r = 0; r < 8; r++) {
                const float4 tv = *reinterpret_cast<const float4*>(trow + r * 32 + x4);
                acc[r] += wv.x * tv.x + wv.y * tv.y + wv.z * tv.z + wv.w * tv.w;
            }
        }

        float* __restrict__ ob =
            out + (size_t)n * (C_ * HOUT * WOUT) + (size_t)(h * 32 + cgrp * 8) * 64 + pos;
        #pragma unroll
        for (int r = 0; r < 8; r++)
            ob[(size_t)r * 64] = acc[r];
    }
}

extern "C" void kernel_launch(void* const* d_in, const int* in_sizes, int n_in,
                              void* d_out, int out_size) {
    const float* feats      = (const float*)d_in[0];
    const int*   batch_idxs = (const int*)d_in[1];
    const int*   starts     = (const int*)d_in[2];
    const int*   goals      = (const int*)d_in[3];
    float*       out        = (float*)d_out;

    const int N = in_sizes[1];   // number of boxes (1024)

    dim3 grid(N, 2);
    roi_kernel<<<grid, 256>>>(feats, batch_idxs, starts, goals, out);
}